// round 9
// baseline (speedup 1.0000x reference)
#include <cuda_runtime.h>
#include <math.h>

#define BB 2
#define CC 128
#define TT 512
#define FF 64
#define HH 32
#define DD 32

typedef unsigned long long u64;

// -------- f32x2 packed-FMA helpers (sm_103a) --------
__device__ __forceinline__ u64 pack2(float lo, float hi) {
    u64 r; asm("mov.b64 %0,{%1,%2};" : "=l"(r) : "f"(lo), "f"(hi)); return r;
}
__device__ __forceinline__ void unpack2(u64 v, float& a, float& b) {
    asm("mov.b64 {%0,%1},%2;" : "=f"(a), "=f"(b) : "l"(v));
}
__device__ __forceinline__ u64 fma2(u64 a, u64 b, u64 c) {
    u64 d; asm("fma.rn.f32x2 %0,%1,%2,%3;" : "=l"(d) : "l"(a), "l"(b), "l"(c)); return d;
}

// -------- scratch (device globals: allocation-free) --------
__device__ float g_xm1[BB*HH*TT*FF];   // (b,h,t,f)
__device__ float g_xf1[BB*HH*TT*FF];   // (b,h,t,f)
__device__ float g_corr[BB*HH*TT*DD];  // (b,h,t,d)
__device__ float g_w[BB*TT*DD];        // (b,t,d) softmax weights
__device__ u64   g_swq[BB*8*2240];     // packed dup weights per (b, 64-t tile)

// ============================================================
// K1 (fused both projections): out[b,h,t,f] = sum_c x[b,c,t,f]*w[c,h] + bias[h]
// 1 t-row per thread (16 u64 accs, ~55 regs) -> ~2x occupancy vs 2-row.
// grid dim3(256, 2): blockIdx.y selects projection; 4 t per block.
// ============================================================
__global__ void __launch_bounds__(256) proj_kernel(
    const float* __restrict__ xm, const float* __restrict__ xf,
    const float* __restrict__ w1, const float* __restrict__ b1,
    const float* __restrict__ w2, const float* __restrict__ b2)
{
    __shared__ __align__(16) float ws[CC*HH];   // [c][h]
    __shared__ float bs[HH];
    int which = blockIdx.y;
    const float* x    = which ? xf : xm;
    const float* w    = which ? w2 : w1;
    const float* bias = which ? b2 : b1;
    float* outg = which ? g_xf1 : g_xm1;

    int tid = threadIdx.x;
    for (int i = tid; i < CC*HH; i += 256) ws[i] = w[i];
    if (tid < HH) bs[tid] = bias[tid];
    __syncthreads();

    int f  = tid & 63;
    int tq = tid >> 6;                 // 0..3
    int bx = blockIdx.x;               // 0..255
    int b  = bx >> 7;
    int t  = ((bx & 127) << 2) + tq;   // 0..511

    u64 acc[16];
#pragma unroll
    for (int i = 0; i < 16; i++) acc[i] = 0ull;

    const float* xp = x + ((size_t)b*CC*TT + t)*FF + f;

#pragma unroll 1
    for (int c0 = 0; c0 < CC; c0 += 8) {
        float v[8];
#pragma unroll
        for (int j = 0; j < 8; j++)
            v[j] = xp[(size_t)(c0+j)*TT*FF];
#pragma unroll
        for (int j = 0; j < 8; j++) {
            u64 pv = pack2(v[j], v[j]);
            const ulonglong2* wq = (const ulonglong2*)(ws + (c0+j)*HH);
#pragma unroll
            for (int q = 0; q < 8; q++) {
                ulonglong2 wv = wq[q];
                acc[2*q]   = fma2(pv, wv.x, acc[2*q]);
                acc[2*q+1] = fma2(pv, wv.y, acc[2*q+1]);
            }
        }
    }

#pragma unroll
    for (int q = 0; q < 16; q++) {
        float a0, a1;
        unpack2(acc[q], a0, a1);
        int h0 = 2*q, h1 = 2*q+1;
        outg[((size_t)(b*HH+h0)*TT + t)*FF + f] = a0 + bs[h0];
        outg[((size_t)(b*HH+h1)*TT + t)*FF + f] = a1 + bs[h1];
    }
}

// ============================================================
// K2: banded correlation (register-tiled band-GEMM) — unchanged
// ============================================================
#define K2T 64
#define K2S 70
__global__ void __launch_bounds__(256) corr_kernel()
{
    __shared__ float sm[K2T*K2S];
    __shared__ float sf[(K2T+31)*K2S];

    int b = blockIdx.z, h = blockIdx.y, t0 = blockIdx.x * K2T;
    int tid = threadIdx.x;   // 256

    const float* xmp = g_xm1 + ((size_t)(b*HH+h)*TT)*FF;
    const float* xfp = g_xf1 + ((size_t)(b*HH+h)*TT)*FF;

    for (int i = tid; i < K2T*FF; i += 256) {
        int r = i >> 6, fc = i & 63;
        sm[r*K2S + fc] = xmp[(size_t)(t0+r)*FF + fc];
    }
    for (int i = tid; i < (K2T+31)*FF; i += 256) {
        int r = i >> 6, fc = i & 63;
        int tt = t0 + r - 31;
        sf[r*K2S + fc] = (tt >= 0) ? xfp[(size_t)tt*FF + fc] : 0.f;
    }
    __syncthreads();

    int tl0 = (tid >> 3) << 1;   // 0,2,...,62
    int d0  = (tid & 7)  << 2;   // 0,4,...,28

    u64 acc[2][4];
#pragma unroll
    for (int i = 0; i < 2; i++)
#pragma unroll
        for (int j = 0; j < 4; j++) acc[i][j] = 0ull;

#pragma unroll 4
    for (int fcp = 0; fcp < FF/2; fcp++) {
        u64 a[2], br[5];
#pragma unroll
        for (int i = 0; i < 2; i++)
            a[i] = *(const u64*)(sm + (tl0+i)*K2S + fcp*2);
#pragma unroll
        for (int k = 0; k < 5; k++)
            br[k] = *(const u64*)(sf + (tl0+d0+k)*K2S + fcp*2);
#pragma unroll
        for (int i = 0; i < 2; i++)
#pragma unroll
            for (int j = 0; j < 4; j++)
                acc[i][j] = fma2(a[i], br[i+j], acc[i][j]);
    }

#pragma unroll
    for (int i = 0; i < 2; i++) {
        float4 v; float x0, x1;
        unpack2(acc[i][0], x0, x1); v.x = x0 + x1;
        unpack2(acc[i][1], x0, x1); v.y = x0 + x1;
        unpack2(acc[i][2], x0, x1); v.z = x0 + x1;
        unpack2(acc[i][3], x0, x1); v.w = x0 + x1;
        *(float4*)(g_corr + (((size_t)(b*HH+h)*TT + (t0+tl0+i))*DD + d0)) = v;
    }
}

// ============================================================
// K3: conv + mask + softmax — unchanged
// ============================================================
__global__ void conv_softmax_kernel(const float* __restrict__ wc,
                                    const float* __restrict__ bc)
{
    __shared__ float sc[16][12*36];
    __shared__ float wcs[HH*15];
    int tid = threadIdx.x;  // 256
    int b = blockIdx.y, t0 = blockIdx.x * 8;

    for (int i = tid; i < HH*15; i += 256) wcs[i] = wc[i];

    int d  = tid & 31;
    int tl = tid >> 5;
    float acc = 0.f;

#pragma unroll 1
    for (int ph = 0; ph < 2; ph++) {
        __syncthreads();
        const float* cpb = g_corr + ((size_t)(b*HH + ph*16)*TT)*DD;
        for (int i = tid; i < 16*12*34; i += 256) {
            int h   = i / 408;
            int rem = i - h*408;
            int r   = rem / 34;
            int col = rem - r*34;
            int tt = t0 - 3 + r, dd = col - 1;
            float v = 0.f;
            if (tt >= 0 && tt < TT && dd >= 0 && dd < DD)
                v = cpb[(size_t)h*TT*DD + (size_t)tt*DD + dd];
            sc[h][r*36 + col] = v;
        }
        __syncthreads();
#pragma unroll 1
        for (int h = 0; h < 16; h++) {
            const float* s  = sc[h] + tl*36 + d;
            const float* wv = wcs + (ph*16 + h)*15;
#pragma unroll
            for (int kh = 0; kh < 5; kh++)
#pragma unroll
                for (int kw = 0; kw < 3; kw++)
                    acc = fmaf(s[kh*36 + kw], wv[kh*3 + kw], acc);
        }
    }

    acc += bc[0];
    int t = t0 + tl;
    if (t + d < DD - 1) acc = -1e13f;

    float m = acc;
#pragma unroll
    for (int o = 16; o; o >>= 1) m = fmaxf(m, __shfl_xor_sync(0xffffffffu, m, o));
    float e = expf(acc - m);
    float s = e;
#pragma unroll
    for (int o = 16; o; o >>= 1) s += __shfl_xor_sync(0xffffffffu, s, o);

    g_w[((size_t)b*TT + t)*DD + d] = e / s;
}

// ============================================================
// K3b: build packed duplicated weights once per (b, 64-t tile).
// g_swq[(b*8+tile)*2240 + tg*140 + rl*4 + i]
//   = dup pair of w[b, tile*64 + tg*4 + i, rl - i]  (0 outside [0,32))
// ============================================================
__global__ void swq_build_kernel()
{
    int bt = blockIdx.x;           // 0..15 = b*8 + tile
    int b  = bt >> 3;
    int t0 = (bt & 7) * K2T;
    const float* wp = g_w + ((size_t)b*TT + t0)*DD;
    u64* dst = g_swq + (size_t)bt*2240;
    for (int i = threadIdx.x; i < 2240; i += 256) {
        int tg  = i / 140;
        int rem = i - tg*140;
        int rl  = rem >> 2;
        int ii  = rem & 3;
        int dd  = rl - ii;
        float v = (dd >= 0 && dd < DD) ? wp[((tg << 2) + ii)*DD + dd] : 0.f;
        dst[i] = pack2(v, v);
    }
}

// ============================================================
// K4: out[b,c,t,f] = sum_d w[b,t,d] * xf[b,c,t+d-31,f]
// Staging now pure vectorized copies (float4 LDG for sx, flat uint4 copy
// of precomputed g_swq) -> staging ALU/instructions cut ~4x.
// Inner loop: R7 software-pipelined, zero predicates.
// ============================================================
#define K4T 64
__global__ void __launch_bounds__(256) out_kernel(const float* __restrict__ xf,
                                                  float* __restrict__ out)
{
    __shared__ __align__(16) float sx[(K4T+31)*FF];  // 24320 B
    __shared__ __align__(16) u64 swq[2240];          // 17920 B

    int b = blockIdx.z, c = blockIdx.y, tile = blockIdx.x;
    int t0 = tile * K4T;
    int tid = threadIdx.x;  // 256

    // sx staging: float4 vectorized; rows t0-31 .. t0+63
    {
        const float4* xp4 = (const float4*)(xf + ((size_t)(b*CC + c)*TT)*FF);
        float4* sx4 = (float4*)sx;
        int base4 = (t0 - 31) * (FF/4);   // may be negative
#pragma unroll
        for (int k = 0; k < 6; k++) {
            int i = tid + k*256;          // 0 .. 1535; need < 95*16 = 1520
            if (i < (K4T+31)*(FF/4)) {
                int src = base4 + i;
                sx4[i] = (src >= 0) ? xp4[src]
                                    : make_float4(0.f, 0.f, 0.f, 0.f);
            }
        }
    }
    // swq staging: flat coalesced copy of precomputed tile (1120 uint4)
    {
        const uint4* src = (const uint4*)(g_swq + (size_t)(b*8 + tile)*2240);
        uint4* dst = (uint4*)swq;
#pragma unroll
        for (int k = 0; k < 5; k++) {
            int i = tid + k*256;          // 0 .. 1279; need < 1120
            if (i < 1120) dst[i] = src[i];
        }
    }
    __syncthreads();

    int fq = tid & 15;            // f = 4*fq .. 4*fq+3
    int tg = tid >> 4;            // 0..15
    int tb = tg << 2;             // t_local base

    u64 acc[4][2];
#pragma unroll
    for (int i = 0; i < 4; i++) { acc[i][0] = 0ull; acc[i][1] = 0ull; }

    const float* xrow = sx + tb*FF + fq*4;
    const ulonglong2* wq = (const ulonglong2*)(swq + (size_t)tg*140);

    // software pipeline: preload iter 0, rotate
    ulonglong2 xv = *(const ulonglong2*)(xrow);
    ulonglong2 q0 = wq[0];
    ulonglong2 q1 = wq[1];

#pragma unroll
    for (int rl = 0; rl < 34; rl++) {
        ulonglong2 xv_n = *(const ulonglong2*)(xrow + (rl+1)*FF);
        ulonglong2 q0_n = wq[(rl+1)*2];
        ulonglong2 q1_n = wq[(rl+1)*2 + 1];
        acc[0][0] = fma2(xv.x, q0.x, acc[0][0]);
        acc[0][1] = fma2(xv.y, q0.x, acc[0][1]);
        acc[1][0] = fma2(xv.x, q0.y, acc[1][0]);
        acc[1][1] = fma2(xv.y, q0.y, acc[1][1]);
        acc[2][0] = fma2(xv.x, q1.x, acc[2][0]);
        acc[2][1] = fma2(xv.y, q1.x, acc[2][1]);
        acc[3][0] = fma2(xv.x, q1.y, acc[3][0]);
        acc[3][1] = fma2(xv.y, q1.y, acc[3][1]);
        xv = xv_n; q0 = q0_n; q1 = q1_n;
    }
    acc[0][0] = fma2(xv.x, q0.x, acc[0][0]);
    acc[0][1] = fma2(xv.y, q0.x, acc[0][1]);
    acc[1][0] = fma2(xv.x, q0.y, acc[1][0]);
    acc[1][1] = fma2(xv.y, q0.y, acc[1][1]);
    acc[2][0] = fma2(xv.x, q1.x, acc[2][0]);
    acc[2][1] = fma2(xv.y, q1.x, acc[2][1]);
    acc[3][0] = fma2(xv.x, q1.y, acc[3][0]);
    acc[3][1] = fma2(xv.y, q1.y, acc[3][1]);

    float* op = out + ((size_t)(b*CC + c)*TT + (t0 + tb))*FF + fq*4;
#pragma unroll
    for (int i = 0; i < 4; i++) {
        float4 v;
        unpack2(acc[i][0], v.x, v.y);
        unpack2(acc[i][1], v.z, v.w);
        *(float4*)(op + (size_t)i*FF) = v;
    }
}

// ============================================================
extern "C" void kernel_launch(void* const* d_in, const int* in_sizes, int n_in,
                              void* d_out, int out_size)
{
    const float* xm = (const float*)d_in[0];
    const float* xf = (const float*)d_in[1];
    const float* w1 = (const float*)d_in[2];
    const float* b1 = (const float*)d_in[3];
    const float* w2 = (const float*)d_in[4];
    const float* b2 = (const float*)d_in[5];
    const float* wc = (const float*)d_in[6];
    const float* bc = (const float*)d_in[7];
    float* out = (float*)d_out;

    (void)in_sizes; (void)n_in; (void)out_size;

    proj_kernel<<<dim3(256, 2), 256>>>(xm, xf, w1, b1, w2, b2);

    dim3 g2(TT/K2T, HH, BB);
    corr_kernel<<<g2, 256>>>();

    dim3 g3(TT/8, BB);
    conv_softmax_kernel<<<g3, 256>>>(wc, bc);

    swq_build_kernel<<<16, 256>>>();

    dim3 g4(TT/K4T, CC, BB);
    out_kernel<<<g4, 256>>>(xf, out);
}

// round 10
// speedup vs baseline: 1.2813x; 1.2813x over previous
#include <cuda_runtime.h>
#include <math.h>

#define BB 2
#define CC 128
#define TT 512
#define FF 64
#define HH 32
#define DD 32

typedef unsigned long long u64;

// -------- f32x2 packed-FMA helpers (sm_103a) --------
__device__ __forceinline__ u64 pack2(float lo, float hi) {
    u64 r; asm("mov.b64 %0,{%1,%2};" : "=l"(r) : "f"(lo), "f"(hi)); return r;
}
__device__ __forceinline__ void unpack2(u64 v, float& a, float& b) {
    asm("mov.b64 {%0,%1},%2;" : "=f"(a), "=f"(b) : "l"(v));
}
__device__ __forceinline__ u64 fma2(u64 a, u64 b, u64 c) {
    u64 d; asm("fma.rn.f32x2 %0,%1,%2,%3;" : "=l"(d) : "l"(a), "l"(b), "l"(c)); return d;
}

// -------- scratch (device globals: allocation-free) --------
__device__ float g_xm1[BB*HH*TT*FF];   // (b,h,t,f)
__device__ float g_xf1[BB*HH*TT*FF];   // (b,h,t,f)
__device__ float g_corr[BB*HH*TT*DD];  // (b,h,t,d)
__device__ u64   g_swq[BB*8*2240];     // packed dup softmax weights per (b, 64-t tile)

// ============================================================
// K1 (fused both projections): out[b,h,t,f] = sum_c x[b,c,t,f]*w[c,h] + bias[h]
// (exact R8/R4 config: 256 threads, dim3(128,2), 2 t-rows per thread)
// ============================================================
__global__ void __launch_bounds__(256) proj_kernel(
    const float* __restrict__ xm, const float* __restrict__ xf,
    const float* __restrict__ w1, const float* __restrict__ b1,
    const float* __restrict__ w2, const float* __restrict__ b2)
{
    __shared__ __align__(16) float ws[CC*HH];   // [c][h]
    __shared__ float bs[HH];
    int which = blockIdx.y;
    const float* x    = which ? xf : xm;
    const float* w    = which ? w2 : w1;
    const float* bias = which ? b2 : b1;
    float* outg = which ? g_xf1 : g_xm1;

    int tid = threadIdx.x;
    for (int i = tid; i < CC*HH; i += 256) ws[i] = w[i];
    if (tid < HH) bs[tid] = bias[tid];
    __syncthreads();

    int f  = tid & 63;
    int tp = tid >> 6;                       // 0..3
    int bx = blockIdx.x;
    int b  = bx >> 6;
    int t  = (((bx & 63) << 2) + tp) << 1;   // even t; thread does t and t+1

    u64 acc0[16], acc1[16];
#pragma unroll
    for (int i = 0; i < 16; i++) { acc0[i] = 0ull; acc1[i] = 0ull; }

    const float* xp = x + ((size_t)b*CC*TT + t)*FF + f;

#pragma unroll 1
    for (int c0 = 0; c0 < CC; c0 += 8) {
        float va[8], vb[8];
#pragma unroll
        for (int j = 0; j < 8; j++) {
            const float* p = xp + (size_t)(c0+j)*TT*FF;
            va[j] = p[0];
            vb[j] = p[FF];
        }
#pragma unroll
        for (int j = 0; j < 8; j++) {
            u64 pa = pack2(va[j], va[j]);
            u64 pb = pack2(vb[j], vb[j]);
            const ulonglong2* wq = (const ulonglong2*)(ws + (c0+j)*HH);
#pragma unroll
            for (int q = 0; q < 8; q++) {
                ulonglong2 wv = wq[q];
                acc0[2*q]   = fma2(pa, wv.x, acc0[2*q]);
                acc0[2*q+1] = fma2(pa, wv.y, acc0[2*q+1]);
                acc1[2*q]   = fma2(pb, wv.x, acc1[2*q]);
                acc1[2*q+1] = fma2(pb, wv.y, acc1[2*q+1]);
            }
        }
    }

#pragma unroll
    for (int q = 0; q < 16; q++) {
        float a0, a1, c0v, c1v;
        unpack2(acc0[q], a0, a1);
        unpack2(acc1[q], c0v, c1v);
        int h0 = 2*q, h1 = 2*q+1;
        float* o0 = outg + ((size_t)(b*HH+h0)*TT + t)*FF + f;
        float* o1 = outg + ((size_t)(b*HH+h1)*TT + t)*FF + f;
        o0[0]  = a0  + bs[h0];
        o0[FF] = c0v + bs[h0];
        o1[0]  = a1  + bs[h1];
        o1[FF] = c1v + bs[h1];
    }
}

// ============================================================
// K2: banded correlation (register-tiled band-GEMM) — unchanged
// ============================================================
#define K2T 64
#define K2S 70
__global__ void __launch_bounds__(256) corr_kernel()
{
    __shared__ float sm[K2T*K2S];
    __shared__ float sf[(K2T+31)*K2S];

    int b = blockIdx.z, h = blockIdx.y, t0 = blockIdx.x * K2T;
    int tid = threadIdx.x;   // 256

    const float* xmp = g_xm1 + ((size_t)(b*HH+h)*TT)*FF;
    const float* xfp = g_xf1 + ((size_t)(b*HH+h)*TT)*FF;

    for (int i = tid; i < K2T*FF; i += 256) {
        int r = i >> 6, fc = i & 63;
        sm[r*K2S + fc] = xmp[(size_t)(t0+r)*FF + fc];
    }
    for (int i = tid; i < (K2T+31)*FF; i += 256) {
        int r = i >> 6, fc = i & 63;
        int tt = t0 + r - 31;
        sf[r*K2S + fc] = (tt >= 0) ? xfp[(size_t)tt*FF + fc] : 0.f;
    }
    __syncthreads();

    int tl0 = (tid >> 3) << 1;   // 0,2,...,62
    int d0  = (tid & 7)  << 2;   // 0,4,...,28

    u64 acc[2][4];
#pragma unroll
    for (int i = 0; i < 2; i++)
#pragma unroll
        for (int j = 0; j < 4; j++) acc[i][j] = 0ull;

#pragma unroll 4
    for (int fcp = 0; fcp < FF/2; fcp++) {
        u64 a[2], br[5];
#pragma unroll
        for (int i = 0; i < 2; i++)
            a[i] = *(const u64*)(sm + (tl0+i)*K2S + fcp*2);
#pragma unroll
        for (int k = 0; k < 5; k++)
            br[k] = *(const u64*)(sf + (tl0+d0+k)*K2S + fcp*2);
#pragma unroll
        for (int i = 0; i < 2; i++)
#pragma unroll
            for (int j = 0; j < 4; j++)
                acc[i][j] = fma2(a[i], br[i+j], acc[i][j]);
    }

#pragma unroll
    for (int i = 0; i < 2; i++) {
        float4 v; float x0, x1;
        unpack2(acc[i][0], x0, x1); v.x = x0 + x1;
        unpack2(acc[i][1], x0, x1); v.y = x0 + x1;
        unpack2(acc[i][2], x0, x1); v.z = x0 + x1;
        unpack2(acc[i][3], x0, x1); v.w = x0 + x1;
        *(float4*)(g_corr + (((size_t)(b*HH+h)*TT + (t0+tl0+i))*DD + d0)) = v;
    }
}

// ============================================================
// K3: conv + mask + softmax. Writes softmax weights DIRECTLY into the
// packed duplicated g_swq layout K4 consumes (no separate build kernel,
// g_w eliminated). Each thread owns one (b,t,d): unique slot
// (tile, tg, ii from t; rl = d + ii). Threads with d<3 zero the 3
// invalid pad slots of their t (rl = k<ii ? k : 32+k).
// ============================================================
__global__ void conv_softmax_kernel(const float* __restrict__ wc,
                                    const float* __restrict__ bc)
{
    __shared__ float sc[16][12*36];
    __shared__ float wcs[HH*15];
    int tid = threadIdx.x;  // 256
    int b = blockIdx.y, t0 = blockIdx.x * 8;

    for (int i = tid; i < HH*15; i += 256) wcs[i] = wc[i];

    int d  = tid & 31;
    int tl = tid >> 5;
    float acc = 0.f;

#pragma unroll 1
    for (int ph = 0; ph < 2; ph++) {
        __syncthreads();
        const float* cpb = g_corr + ((size_t)(b*HH + ph*16)*TT)*DD;
        for (int i = tid; i < 16*12*34; i += 256) {
            int h   = i / 408;
            int rem = i - h*408;
            int r   = rem / 34;
            int col = rem - r*34;
            int tt = t0 - 3 + r, dd = col - 1;
            float v = 0.f;
            if (tt >= 0 && tt < TT && dd >= 0 && dd < DD)
                v = cpb[(size_t)h*TT*DD + (size_t)tt*DD + dd];
            sc[h][r*36 + col] = v;
        }
        __syncthreads();
#pragma unroll 1
        for (int h = 0; h < 16; h++) {
            const float* s  = sc[h] + tl*36 + d;
            const float* wv = wcs + (ph*16 + h)*15;
#pragma unroll
            for (int kh = 0; kh < 5; kh++)
#pragma unroll
                for (int kw = 0; kw < 3; kw++)
                    acc = fmaf(s[kh*36 + kw], wv[kh*3 + kw], acc);
        }
    }

    acc += bc[0];
    int t = t0 + tl;
    if (t + d < DD - 1) acc = -1e13f;

    float m = acc;
#pragma unroll
    for (int o = 16; o; o >>= 1) m = fmaxf(m, __shfl_xor_sync(0xffffffffu, m, o));
    float e = expf(acc - m);
    float s = e;
#pragma unroll
    for (int o = 16; o; o >>= 1) s += __shfl_xor_sync(0xffffffffu, s, o);

    float wv = e / s;

    // scatter into packed layout: g_swq[(b*8+tile)*2240 + tg*140 + rl*4 + ii]
    int tile = t >> 6;
    int tg   = (t >> 2) & 15;
    int ii   = t & 3;
    u64* base = g_swq + (size_t)(b*8 + tile)*2240 + tg*140;
    base[(d + ii)*4 + ii] = pack2(wv, wv);
    if (d < 3) {
        int rl = (d < ii) ? d : 32 + d;
        base[rl*4 + ii] = 0ull;
    }
}

// ============================================================
// K4: out[b,c,t,f] = sum_d w[b,t,d] * xf[b,c,t+d-31,f]
// Staging: float4 LDG for sx + flat uint4 copy of precomputed g_swq
// (no div/mod/pack ALU). Inner loop: software-pipelined, zero predicates.
// ============================================================
#define K4T 64
__global__ void __launch_bounds__(256) out_kernel(const float* __restrict__ xf,
                                                  float* __restrict__ out)
{
    __shared__ __align__(16) float sx[(K4T+31)*FF];  // 24320 B
    __shared__ __align__(16) u64 swq[2240];          // 17920 B

    int b = blockIdx.z, c = blockIdx.y, tile = blockIdx.x;
    int t0 = tile * K4T;
    int tid = threadIdx.x;  // 256

    // sx staging: float4 vectorized; rows t0-31 .. t0+63
    {
        const float4* xp4 = (const float4*)(xf + ((size_t)(b*CC + c)*TT)*FF);
        float4* sx4 = (float4*)sx;
        int base4 = (t0 - 31) * (FF/4);   // may be negative
#pragma unroll
        for (int k = 0; k < 6; k++) {
            int i = tid + k*256;          // 0 .. 1535; need < 95*16 = 1520
            if (i < (K4T+31)*(FF/4)) {
                int src = base4 + i;
                sx4[i] = (src >= 0) ? xp4[src]
                                    : make_float4(0.f, 0.f, 0.f, 0.f);
            }
        }
    }
    // swq staging: flat coalesced copy of precomputed tile (1120 uint4)
    {
        const uint4* src = (const uint4*)(g_swq + (size_t)(b*8 + tile)*2240);
        uint4* dst = (uint4*)swq;
#pragma unroll
        for (int k = 0; k < 5; k++) {
            int i = tid + k*256;          // 0 .. 1279; need < 1120
            if (i < 1120) dst[i] = src[i];
        }
    }
    __syncthreads();

    int fq = tid & 15;            // f = 4*fq .. 4*fq+3
    int tg = tid >> 4;            // 0..15
    int tb = tg << 2;             // t_local base

    u64 acc[4][2];
#pragma unroll
    for (int i = 0; i < 4; i++) { acc[i][0] = 0ull; acc[i][1] = 0ull; }

    const float* xrow = sx + tb*FF + fq*4;
    const ulonglong2* wq = (const ulonglong2*)(swq + (size_t)tg*140);

    // software pipeline: preload iter 0, rotate
    ulonglong2 xv = *(const ulonglong2*)(xrow);
    ulonglong2 q0 = wq[0];
    ulonglong2 q1 = wq[1];

#pragma unroll
    for (int rl = 0; rl < 34; rl++) {
        ulonglong2 xv_n = *(const ulonglong2*)(xrow + (rl+1)*FF);
        ulonglong2 q0_n = wq[(rl+1)*2];
        ulonglong2 q1_n = wq[(rl+1)*2 + 1];
        acc[0][0] = fma2(xv.x, q0.x, acc[0][0]);
        acc[0][1] = fma2(xv.y, q0.x, acc[0][1]);
        acc[1][0] = fma2(xv.x, q0.y, acc[1][0]);
        acc[1][1] = fma2(xv.y, q0.y, acc[1][1]);
        acc[2][0] = fma2(xv.x, q1.x, acc[2][0]);
        acc[2][1] = fma2(xv.y, q1.x, acc[2][1]);
        acc[3][0] = fma2(xv.x, q1.y, acc[3][0]);
        acc[3][1] = fma2(xv.y, q1.y, acc[3][1]);
        xv = xv_n; q0 = q0_n; q1 = q1_n;
    }
    acc[0][0] = fma2(xv.x, q0.x, acc[0][0]);
    acc[0][1] = fma2(xv.y, q0.x, acc[0][1]);
    acc[1][0] = fma2(xv.x, q0.y, acc[1][0]);
    acc[1][1] = fma2(xv.y, q0.y, acc[1][1]);
    acc[2][0] = fma2(xv.x, q1.x, acc[2][0]);
    acc[2][1] = fma2(xv.y, q1.x, acc[2][1]);
    acc[3][0] = fma2(xv.x, q1.y, acc[3][0]);
    acc[3][1] = fma2(xv.y, q1.y, acc[3][1]);

    float* op = out + ((size_t)(b*CC + c)*TT + (t0 + tb))*FF + fq*4;
#pragma unroll
    for (int i = 0; i < 4; i++) {
        float4 v;
        unpack2(acc[i][0], v.x, v.y);
        unpack2(acc[i][1], v.z, v.w);
        *(float4*)(op + (size_t)i*FF) = v;
    }
}

// ============================================================
extern "C" void kernel_launch(void* const* d_in, const int* in_sizes, int n_in,
                              void* d_out, int out_size)
{
    const float* xm = (const float*)d_in[0];
    const float* xf = (const float*)d_in[1];
    const float* w1 = (const float*)d_in[2];
    const float* b1 = (const float*)d_in[3];
    const float* w2 = (const float*)d_in[4];
    const float* b2 = (const float*)d_in[5];
    const float* wc = (const float*)d_in[6];
    const float* bc = (const float*)d_in[7];
    float* out = (float*)d_out;

    (void)in_sizes; (void)n_in; (void)out_size;

    proj_kernel<<<dim3(128, 2), 256>>>(xm, xf, w1, b1, w2, b2);

    dim3 g2(TT/K2T, HH, BB);
    corr_kernel<<<g2, 256>>>();

    dim3 g3(TT/8, BB);
    conv_softmax_kernel<<<g3, 256>>>(wc, bc);

    dim3 g4(TT/K4T, CC, BB);
    out_kernel<<<g4, 256>>>(xf, out);
}

// round 11
// speedup vs baseline: 1.3156x; 1.0268x over previous
#include <cuda_runtime.h>
#include <math.h>

#define BB 2
#define CC 128
#define TT 512
#define FF 64
#define HH 32
#define DD 32

typedef unsigned long long u64;

// -------- f32x2 packed-FMA helpers (sm_103a) --------
__device__ __forceinline__ u64 pack2(float lo, float hi) {
    u64 r; asm("mov.b64 %0,{%1,%2};" : "=l"(r) : "f"(lo), "f"(hi)); return r;
}
__device__ __forceinline__ void unpack2(u64 v, float& a, float& b) {
    asm("mov.b64 {%0,%1},%2;" : "=f"(a), "=f"(b) : "l"(v));
}
__device__ __forceinline__ u64 fma2(u64 a, u64 b, u64 c) {
    u64 d; asm("fma.rn.f32x2 %0,%1,%2,%3;" : "=l"(d) : "l"(a), "l"(b), "l"(c)); return d;
}

// -------- scratch (device globals: allocation-free) --------
__device__ float g_xm1[BB*HH*TT*FF];   // (b,h,t,f)
__device__ float g_xf1[BB*HH*TT*FF];   // (b,h,t,f)
__device__ float g_corr[BB*HH*TT*DD];  // (b,h,t,d)
// packed dup softmax weights, 8t-group layout:
// g_swq[(b*8+tile)*2496 + tg*312 + rl*8 + ii], tg in [0,8), rl in [0,39), ii in [0,8)
//   = dup pair of w[b, tile*64 + tg*8 + ii, rl - ii]  (0 outside [0,32))
__device__ u64   g_swq[BB*8*2496];

// ============================================================
// K1 (fused both projections) — unchanged (R10)
// ============================================================
__global__ void __launch_bounds__(256) proj_kernel(
    const float* __restrict__ xm, const float* __restrict__ xf,
    const float* __restrict__ w1, const float* __restrict__ b1,
    const float* __restrict__ w2, const float* __restrict__ b2)
{
    __shared__ __align__(16) float ws[CC*HH];   // [c][h]
    __shared__ float bs[HH];
    int which = blockIdx.y;
    const float* x    = which ? xf : xm;
    const float* w    = which ? w2 : w1;
    const float* bias = which ? b2 : b1;
    float* outg = which ? g_xf1 : g_xm1;

    int tid = threadIdx.x;
    for (int i = tid; i < CC*HH; i += 256) ws[i] = w[i];
    if (tid < HH) bs[tid] = bias[tid];
    __syncthreads();

    int f  = tid & 63;
    int tp = tid >> 6;                       // 0..3
    int bx = blockIdx.x;
    int b  = bx >> 6;
    int t  = (((bx & 63) << 2) + tp) << 1;   // even t; thread does t and t+1

    u64 acc0[16], acc1[16];
#pragma unroll
    for (int i = 0; i < 16; i++) { acc0[i] = 0ull; acc1[i] = 0ull; }

    const float* xp = x + ((size_t)b*CC*TT + t)*FF + f;

#pragma unroll 1
    for (int c0 = 0; c0 < CC; c0 += 8) {
        float va[8], vb[8];
#pragma unroll
        for (int j = 0; j < 8; j++) {
            const float* p = xp + (size_t)(c0+j)*TT*FF;
            va[j] = p[0];
            vb[j] = p[FF];
        }
#pragma unroll
        for (int j = 0; j < 8; j++) {
            u64 pa = pack2(va[j], va[j]);
            u64 pb = pack2(vb[j], vb[j]);
            const ulonglong2* wq = (const ulonglong2*)(ws + (c0+j)*HH);
#pragma unroll
            for (int q = 0; q < 8; q++) {
                ulonglong2 wv = wq[q];
                acc0[2*q]   = fma2(pa, wv.x, acc0[2*q]);
                acc0[2*q+1] = fma2(pa, wv.y, acc0[2*q+1]);
                acc1[2*q]   = fma2(pb, wv.x, acc1[2*q]);
                acc1[2*q+1] = fma2(pb, wv.y, acc1[2*q+1]);
            }
        }
    }

#pragma unroll
    for (int q = 0; q < 16; q++) {
        float a0, a1, c0v, c1v;
        unpack2(acc0[q], a0, a1);
        unpack2(acc1[q], c0v, c1v);
        int h0 = 2*q, h1 = 2*q+1;
        float* o0 = outg + ((size_t)(b*HH+h0)*TT + t)*FF + f;
        float* o1 = outg + ((size_t)(b*HH+h1)*TT + t)*FF + f;
        o0[0]  = a0  + bs[h0];
        o0[FF] = c0v + bs[h0];
        o1[0]  = a1  + bs[h1];
        o1[FF] = c1v + bs[h1];
    }
}

// ============================================================
// K2: banded correlation — unchanged (R10)
// ============================================================
#define K2T 64
#define K2S 70
__global__ void __launch_bounds__(256) corr_kernel()
{
    __shared__ float sm[K2T*K2S];
    __shared__ float sf[(K2T+31)*K2S];

    int b = blockIdx.z, h = blockIdx.y, t0 = blockIdx.x * K2T;
    int tid = threadIdx.x;   // 256

    const float* xmp = g_xm1 + ((size_t)(b*HH+h)*TT)*FF;
    const float* xfp = g_xf1 + ((size_t)(b*HH+h)*TT)*FF;

    for (int i = tid; i < K2T*FF; i += 256) {
        int r = i >> 6, fc = i & 63;
        sm[r*K2S + fc] = xmp[(size_t)(t0+r)*FF + fc];
    }
    for (int i = tid; i < (K2T+31)*FF; i += 256) {
        int r = i >> 6, fc = i & 63;
        int tt = t0 + r - 31;
        sf[r*K2S + fc] = (tt >= 0) ? xfp[(size_t)tt*FF + fc] : 0.f;
    }
    __syncthreads();

    int tl0 = (tid >> 3) << 1;   // 0,2,...,62
    int d0  = (tid & 7)  << 2;   // 0,4,...,28

    u64 acc[2][4];
#pragma unroll
    for (int i = 0; i < 2; i++)
#pragma unroll
        for (int j = 0; j < 4; j++) acc[i][j] = 0ull;

#pragma unroll 4
    for (int fcp = 0; fcp < FF/2; fcp++) {
        u64 a[2], br[5];
#pragma unroll
        for (int i = 0; i < 2; i++)
            a[i] = *(const u64*)(sm + (tl0+i)*K2S + fcp*2);
#pragma unroll
        for (int k = 0; k < 5; k++)
            br[k] = *(const u64*)(sf + (tl0+d0+k)*K2S + fcp*2);
#pragma unroll
        for (int i = 0; i < 2; i++)
#pragma unroll
            for (int j = 0; j < 4; j++)
                acc[i][j] = fma2(a[i], br[i+j], acc[i][j]);
    }

#pragma unroll
    for (int i = 0; i < 2; i++) {
        float4 v; float x0, x1;
        unpack2(acc[i][0], x0, x1); v.x = x0 + x1;
        unpack2(acc[i][1], x0, x1); v.y = x0 + x1;
        unpack2(acc[i][2], x0, x1); v.z = x0 + x1;
        unpack2(acc[i][3], x0, x1); v.w = x0 + x1;
        *(float4*)(g_corr + (((size_t)(b*HH+h)*TT + (t0+tl0+i))*DD + d0)) = v;
    }
}

// ============================================================
// K3: conv + mask + softmax; scatters weights directly into the
// 8t-group packed g_swq layout. Thread owns (b,t,d): slot
// (tile = t>>6, tg = (t>>3)&7, ii = t&7, rl = d+ii). Threads with d<7
// zero the 7 invalid pad slots of their t (rl = d<ii ? d : 32+d).
// ============================================================
__global__ void conv_softmax_kernel(const float* __restrict__ wc,
                                    const float* __restrict__ bc)
{
    __shared__ float sc[16][12*36];
    __shared__ float wcs[HH*15];
    int tid = threadIdx.x;  // 256
    int b = blockIdx.y, t0 = blockIdx.x * 8;

    for (int i = tid; i < HH*15; i += 256) wcs[i] = wc[i];

    int d  = tid & 31;
    int tl = tid >> 5;
    float acc = 0.f;

#pragma unroll 1
    for (int ph = 0; ph < 2; ph++) {
        __syncthreads();
        const float* cpb = g_corr + ((size_t)(b*HH + ph*16)*TT)*DD;
        for (int i = tid; i < 16*12*34; i += 256) {
            int h   = i / 408;
            int rem = i - h*408;
            int r   = rem / 34;
            int col = rem - r*34;
            int tt = t0 - 3 + r, dd = col - 1;
            float v = 0.f;
            if (tt >= 0 && tt < TT && dd >= 0 && dd < DD)
                v = cpb[(size_t)h*TT*DD + (size_t)tt*DD + dd];
            sc[h][r*36 + col] = v;
        }
        __syncthreads();
#pragma unroll 1
        for (int h = 0; h < 16; h++) {
            const float* s  = sc[h] + tl*36 + d;
            const float* wv = wcs + (ph*16 + h)*15;
#pragma unroll
            for (int kh = 0; kh < 5; kh++)
#pragma unroll
                for (int kw = 0; kw < 3; kw++)
                    acc = fmaf(s[kh*36 + kw], wv[kh*3 + kw], acc);
        }
    }

    acc += bc[0];
    int t = t0 + tl;
    if (t + d < DD - 1) acc = -1e13f;

    float m = acc;
#pragma unroll
    for (int o = 16; o; o >>= 1) m = fmaxf(m, __shfl_xor_sync(0xffffffffu, m, o));
    float e = expf(acc - m);
    float s = e;
#pragma unroll
    for (int o = 16; o; o >>= 1) s += __shfl_xor_sync(0xffffffffu, s, o);

    float wv = e / s;

    // scatter into 8t packed layout
    int tile = t >> 6;
    int tg   = (t >> 3) & 7;
    int ii   = t & 7;
    u64* base = g_swq + (size_t)(b*8 + tile)*2496 + tg*312;
    base[(d + ii)*8 + ii] = pack2(wv, wv);
    if (d < 7) {
        int rl = (d < ii) ? d : 32 + d;
        base[rl*8 + ii] = 0ull;
    }
}

// ============================================================
// K4: out[b,c,t,f] = sum_d w[b,t,d] * xf[b,c,t+d-31,f]
// 256 threads, 2 channels per block; per channel 128 threads =
// 16 f-quads x 8 t-groups of 8 t. Each 16B x-load feeds 16 FFMA2
// (t-reuse 8, was 4) -> crossbar traffic -26%. Zero predicates.
// ============================================================
#define K4T 64
__global__ void __launch_bounds__(256) out_kernel(const float* __restrict__ xf,
                                                  float* __restrict__ out)
{
    __shared__ __align__(16) float sx[2][(K4T+31)*FF];  // 48640 B
    __shared__ __align__(16) u64 swq[2496];              // 19968 B

    int b = blockIdx.z, cpair = blockIdx.y, tile = blockIdx.x;
    int t0 = tile * K4T;
    int tid = threadIdx.x;  // 256

    // sx staging (both channels): float4 vectorized; rows t0-31 .. t0+63
    {
        int base4 = (t0 - 31) * (FF/4);   // may be negative
#pragma unroll
        for (int cs = 0; cs < 2; cs++) {
            const float4* xp4 = (const float4*)(xf + ((size_t)(b*CC + cpair*2 + cs)*TT)*FF);
            float4* sx4 = (float4*)sx[cs];
#pragma unroll
            for (int k = 0; k < 6; k++) {
                int i = tid + k*256;      // need < 95*16 = 1520
                if (i < (K4T+31)*(FF/4)) {
                    int src = base4 + i;
                    sx4[i] = (src >= 0) ? xp4[src]
                                        : make_float4(0.f, 0.f, 0.f, 0.f);
                }
            }
        }
    }
    // swq staging: flat coalesced copy (2496 u64 = 1248 uint4)
    {
        const uint4* src = (const uint4*)(g_swq + (size_t)(b*8 + tile)*2496);
        uint4* dst = (uint4*)swq;
#pragma unroll
        for (int k = 0; k < 5; k++) {
            int i = tid + k*256;          // need < 1248
            if (i < 1248) dst[i] = src[i];
        }
    }
    __syncthreads();

    int cs = tid >> 7;            // channel slice 0/1
    int r  = tid & 127;
    int fq = r & 15;              // f = 4*fq .. 4*fq+3
    int tg = r >> 4;              // 0..7
    int tb = tg << 3;             // t_local base (8 t per thread)

    u64 acc[8][2];
#pragma unroll
    for (int i = 0; i < 8; i++) { acc[i][0] = 0ull; acc[i][1] = 0ull; }

    const float* xrow = sx[cs] + tb*FF + fq*4;
    const ulonglong2* wq = (const ulonglong2*)(swq + (size_t)tg*312);

#pragma unroll 3
    for (int rl = 0; rl < 39; rl++) {
        ulonglong2 xv = *(const ulonglong2*)(xrow + rl*FF);
        ulonglong2 q0 = wq[rl*4];       // ii = 0,1
        ulonglong2 q1 = wq[rl*4 + 1];   // ii = 2,3
        ulonglong2 q2 = wq[rl*4 + 2];   // ii = 4,5
        ulonglong2 q3 = wq[rl*4 + 3];   // ii = 6,7
        acc[0][0] = fma2(xv.x, q0.x, acc[0][0]);
        acc[0][1] = fma2(xv.y, q0.x, acc[0][1]);
        acc[1][0] = fma2(xv.x, q0.y, acc[1][0]);
        acc[1][1] = fma2(xv.y, q0.y, acc[1][1]);
        acc[2][0] = fma2(xv.x, q1.x, acc[2][0]);
        acc[2][1] = fma2(xv.y, q1.x, acc[2][1]);
        acc[3][0] = fma2(xv.x, q1.y, acc[3][0]);
        acc[3][1] = fma2(xv.y, q1.y, acc[3][1]);
        acc[4][0] = fma2(xv.x, q2.x, acc[4][0]);
        acc[4][1] = fma2(xv.y, q2.x, acc[4][1]);
        acc[5][0] = fma2(xv.x, q2.y, acc[5][0]);
        acc[5][1] = fma2(xv.y, q2.y, acc[5][1]);
        acc[6][0] = fma2(xv.x, q3.x, acc[6][0]);
        acc[6][1] = fma2(xv.y, q3.x, acc[6][1]);
        acc[7][0] = fma2(xv.x, q3.y, acc[7][0]);
        acc[7][1] = fma2(xv.y, q3.y, acc[7][1]);
    }

    float* op = out + ((size_t)(b*CC + cpair*2 + cs)*TT + (t0 + tb))*FF + fq*4;
#pragma unroll
    for (int i = 0; i < 8; i++) {
        float4 v;
        unpack2(acc[i][0], v.x, v.y);
        unpack2(acc[i][1], v.z, v.w);
        *(float4*)(op + (size_t)i*FF) = v;
    }
}

// ============================================================
extern "C" void kernel_launch(void* const* d_in, const int* in_sizes, int n_in,
                              void* d_out, int out_size)
{
    const float* xm = (const float*)d_in[0];
    const float* xf = (const float*)d_in[1];
    const float* w1 = (const float*)d_in[2];
    const float* b1 = (const float*)d_in[3];
    const float* w2 = (const float*)d_in[4];
    const float* b2 = (const float*)d_in[5];
    const float* wc = (const float*)d_in[6];
    const float* bc = (const float*)d_in[7];
    float* out = (float*)d_out;

    (void)in_sizes; (void)n_in; (void)out_size;

    proj_kernel<<<dim3(128, 2), 256>>>(xm, xf, w1, b1, w2, b2);

    dim3 g2(TT/K2T, HH, BB);
    corr_kernel<<<g2, 256>>>();

    dim3 g3(TT/8, BB);
    conv_softmax_kernel<<<g3, 256>>>(wc, bc);

    dim3 g4(TT/K4T, CC/2, BB);
    out_kernel<<<g4, 256>>>(xf, out);
}